// round 9
// baseline (speedup 1.0000x reference)
#include <cuda_runtime.h>
#include <cstdint>

// BlockDecomposition RGCN layer, GB300 sm_103a — scatter + smem weight bank.
// out[n] = mask[n]*(xb[n] @ W[16]) + sum_{edges, both dirs} w*(xb[s] @ W[r]) -> t
// xb: (N, 32, 4); blocks: (17, 32, 4, 4)

#define BS 4
#define DIM 128
#define BLK_STRIDE 512       // floats per relation
#define NUM_REL_TOT 17
#define WBANK (NUM_REL_TOT * BLK_STRIDE)   // 8704 floats = 34 KB

__device__ __forceinline__ void red_add_v4(float* p, float4 v) {
    asm volatile("red.global.add.v4.f32 [%0], {%1, %2, %3, %4};"
                 :: "l"(p), "f"(v.x), "f"(v.y), "f"(v.z), "f"(v.w)
                 : "memory");
}

__device__ __forceinline__ float4 block_mm(float4 xv, float4 w0, float4 w1, float4 w2, float4 w3) {
    float4 m;
    m.x = fmaf(xv.x, w0.x, fmaf(xv.y, w1.x, fmaf(xv.z, w2.x, xv.w * w3.x)));
    m.y = fmaf(xv.x, w0.y, fmaf(xv.y, w1.y, fmaf(xv.z, w2.y, xv.w * w3.y)));
    m.z = fmaf(xv.x, w0.z, fmaf(xv.y, w1.z, fmaf(xv.z, w2.z, xv.w * w3.z)));
    m.w = fmaf(xv.x, w0.w, fmaf(xv.y, w1.w, fmaf(xv.z, w2.w, xv.w * w3.w)));
    return m;
}

// Kernel 1: self-loop transform + mask (initializes out).
// Relation-16 weights staged through smem, transposed for conflict-free LDS.
__global__ void __launch_bounds__(256) self_loop_kernel(
    const float* __restrict__ x,
    const int* __restrict__ keep_mask,   // bool materialized as int32
    const float* __restrict__ blocks,
    float* __restrict__ out,
    int n_nodes)
{
    __shared__ float s_w[BLK_STRIDE];
    #pragma unroll
    for (int k = 0; k < 2; k++) {
        int idx = threadIdx.x + k * 256;     // 0..511
        int b = idx >> 4, i = (idx >> 2) & 3, j = idx & 3;
        s_w[i * 128 + b * 4 + j] = blocks[16 * BLK_STRIDE + idx];
    }
    __syncthreads();

    int warp = (blockIdx.x * blockDim.x + threadIdx.x) >> 5;
    int lane = threadIdx.x & 31;
    if (warp >= n_nodes) return;

    const float4 xv = *reinterpret_cast<const float4*>(x + (size_t)warp * DIM + lane * BS);
    const float* wb = s_w + lane * 4;
    float4 w0 = *reinterpret_cast<const float4*>(wb);
    float4 w1 = *reinterpret_cast<const float4*>(wb + 128);
    float4 w2 = *reinterpret_cast<const float4*>(wb + 256);
    float4 w3 = *reinterpret_cast<const float4*>(wb + 384);

    float4 m = block_mm(xv, w0, w1, w2, w3);
    if (keep_mask[warp] == 0) { m.x = 0.f; m.y = 0.f; m.z = 0.f; m.w = 0.f; }
    *reinterpret_cast<float4*>(out + (size_t)warp * DIM + lane * BS) = m;
}

// Kernel 2: TWO edges per warp, both directions each; all-relation weight bank
// staged in smem per block (one-time coalesced copy from `blocks`, transposed).
// Weight fetches ride the smem crossbar instead of L1tex.
__global__ void __launch_bounds__(256) edge_kernel(
    const float* __restrict__ x,
    const int* __restrict__ src,
    const int* __restrict__ tgt,
    const int* __restrict__ etype,
    const float* __restrict__ eweight,
    const float* __restrict__ blocks,
    float* __restrict__ out,
    int n_edges, int half)
{
    __shared__ float s_w[WBANK];   // 34 KB: s_w[r*512 + i*128 + b*4 + j]
    for (int idx = threadIdx.x; idx < WBANK; idx += 256) {
        int r = idx >> 9;
        int rem = idx & 511;
        int b = rem >> 4, i = (rem >> 2) & 3, j = rem & 3;
        s_w[r * BLK_STRIDE + i * 128 + b * 4 + j] = blocks[idx];
    }
    __syncthreads();

    int warp = (blockIdx.x * blockDim.x + threadIdx.x) >> 5;
    int lane = threadIdx.x & 31;
    if (warp >= half) return;

    int e0 = warp;
    int e1 = warp + half;
    bool has1 = (e1 < n_edges);

    int s0 = src[e0], t0 = tgt[e0], r0 = etype[e0];
    float wgt0 = eweight[e0];
    int s1 = s0, t1 = t0, r1 = r0;
    float wgt1 = 0.f;
    if (has1) { s1 = src[e1]; t1 = tgt[e1]; r1 = etype[e1]; wgt1 = eweight[e1]; }

    // issue all 4 x-gathers up front (4 outstanding L2 loads)
    float4 xs0 = *reinterpret_cast<const float4*>(x + (size_t)s0 * DIM + lane * BS);
    float4 xt0 = *reinterpret_cast<const float4*>(x + (size_t)t0 * DIM + lane * BS);
    float4 xs1 = *reinterpret_cast<const float4*>(x + (size_t)s1 * DIM + lane * BS);
    float4 xt1 = *reinterpret_cast<const float4*>(x + (size_t)t1 * DIM + lane * BS);

    // ---- edge 0 ----
    {
        const float* wb = s_w + r0 * BLK_STRIDE + lane * 4;
        float4 w0 = *reinterpret_cast<const float4*>(wb);
        float4 w1 = *reinterpret_cast<const float4*>(wb + 128);
        float4 w2 = *reinterpret_cast<const float4*>(wb + 256);
        float4 w3 = *reinterpret_cast<const float4*>(wb + 384);

        float4 m1 = block_mm(xs0, w0, w1, w2, w3);
        m1.x *= wgt0; m1.y *= wgt0; m1.z *= wgt0; m1.w *= wgt0;
        float4 m2 = block_mm(xt0, w0, w1, w2, w3);
        m2.x *= wgt0; m2.y *= wgt0; m2.z *= wgt0; m2.w *= wgt0;

        red_add_v4(out + (size_t)t0 * DIM + lane * BS, m1);
        red_add_v4(out + (size_t)s0 * DIM + lane * BS, m2);
    }

    // ---- edge 1 ----
    if (has1) {
        const float* wb = s_w + r1 * BLK_STRIDE + lane * 4;
        float4 w0 = *reinterpret_cast<const float4*>(wb);
        float4 w1 = *reinterpret_cast<const float4*>(wb + 128);
        float4 w2 = *reinterpret_cast<const float4*>(wb + 256);
        float4 w3 = *reinterpret_cast<const float4*>(wb + 384);

        float4 m1 = block_mm(xs1, w0, w1, w2, w3);
        m1.x *= wgt1; m1.y *= wgt1; m1.z *= wgt1; m1.w *= wgt1;
        float4 m2 = block_mm(xt1, w0, w1, w2, w3);
        m2.x *= wgt1; m2.y *= wgt1; m2.z *= wgt1; m2.w *= wgt1;

        red_add_v4(out + (size_t)t1 * DIM + lane * BS, m1);
        red_add_v4(out + (size_t)s1 * DIM + lane * BS, m2);
    }
}

extern "C" void kernel_launch(void* const* d_in, const int* in_sizes, int n_in,
                              void* d_out, int out_size)
{
    const float* x      = (const float*)d_in[0];
    const int*   mask   = (const int*)d_in[1];
    const int*   src    = (const int*)d_in[2];
    const int*   tgt    = (const int*)d_in[3];
    const int*   etype  = (const int*)d_in[4];
    const float* ew     = (const float*)d_in[5];
    const float* blocks = (const float*)d_in[6];
    float*       out    = (float*)d_out;

    int n_nodes = in_sizes[0] / DIM;
    int n_edges = in_sizes[2];
    int half = (n_edges + 1) / 2;

    // K1: out init (self-loop + mask)
    {
        int total_threads = n_nodes * 32;
        int grid = (total_threads + 255) / 256;
        self_loop_kernel<<<grid, 256>>>(x, mask, blocks, out, n_nodes);
    }
    // K2: edge messages, 2 edges/warp, smem weight bank, vectorized reductions
    {
        int total_threads = half * 32;
        int grid = (total_threads + 255) / 256;
        edge_kernel<<<grid, 256>>>(x, src, tgt, etype, ew, blocks, out, n_edges, half);
    }
}

// round 10
// speedup vs baseline: 1.6117x; 1.6117x over previous
#include <cuda_runtime.h>
#include <cstdint>

// BlockDecomposition RGCN layer, GB300 sm_103a — persistent scatter + smem weight bank.
// out[n] = mask[n]*(xb[n] @ W[16]) + sum_{edges, both dirs} w*(xb[s] @ W[r]) -> t
// xb: (N, 32, 4); blocks: (17, 32, 4, 4)

#define BS 4
#define DIM 128
#define BLK_STRIDE 512       // floats per relation
#define NUM_REL_TOT 17
#define WBANK (NUM_REL_TOT * BLK_STRIDE)   // 8704 floats = 34 KB
#define EDGE_BLOCKS 888      // 148 SMs x 6 blocks (smem-limited occupancy)

__device__ __forceinline__ void red_add_v4(float* p, float4 v) {
    asm volatile("red.global.add.v4.f32 [%0], {%1, %2, %3, %4};"
                 :: "l"(p), "f"(v.x), "f"(v.y), "f"(v.z), "f"(v.w)
                 : "memory");
}

__device__ __forceinline__ float4 block_mm(float4 xv, float4 w0, float4 w1, float4 w2, float4 w3) {
    float4 m;
    m.x = fmaf(xv.x, w0.x, fmaf(xv.y, w1.x, fmaf(xv.z, w2.x, xv.w * w3.x)));
    m.y = fmaf(xv.x, w0.y, fmaf(xv.y, w1.y, fmaf(xv.z, w2.y, xv.w * w3.y)));
    m.z = fmaf(xv.x, w0.z, fmaf(xv.y, w1.z, fmaf(xv.z, w2.z, xv.w * w3.z)));
    m.w = fmaf(xv.x, w0.w, fmaf(xv.y, w1.w, fmaf(xv.z, w2.w, xv.w * w3.w)));
    return m;
}

// Kernel 1: self-loop transform + mask (initializes out).
// Relation-16 weights staged through smem, transposed for conflict-free LDS.
__global__ void __launch_bounds__(256) self_loop_kernel(
    const float* __restrict__ x,
    const int* __restrict__ keep_mask,   // bool materialized as int32
    const float* __restrict__ blocks,
    float* __restrict__ out,
    int n_nodes)
{
    __shared__ float s_w[BLK_STRIDE];
    #pragma unroll
    for (int k = 0; k < 2; k++) {
        int idx = threadIdx.x + k * 256;     // 0..511
        int b = idx >> 4, i = (idx >> 2) & 3, j = idx & 3;
        s_w[i * 128 + b * 4 + j] = blocks[16 * BLK_STRIDE + idx];
    }
    __syncthreads();

    int warp = (blockIdx.x * blockDim.x + threadIdx.x) >> 5;
    int lane = threadIdx.x & 31;
    if (warp >= n_nodes) return;

    const float4 xv = *reinterpret_cast<const float4*>(x + (size_t)warp * DIM + lane * BS);
    const float* wb = s_w + lane * 4;
    float4 w0 = *reinterpret_cast<const float4*>(wb);
    float4 w1 = *reinterpret_cast<const float4*>(wb + 128);
    float4 w2 = *reinterpret_cast<const float4*>(wb + 256);
    float4 w3 = *reinterpret_cast<const float4*>(wb + 384);

    float4 m = block_mm(xv, w0, w1, w2, w3);
    if (keep_mask[warp] == 0) { m.x = 0.f; m.y = 0.f; m.z = 0.f; m.w = 0.f; }
    *reinterpret_cast<float4*>(out + (size_t)warp * DIM + lane * BS) = m;
}

// Kernel 2: PERSISTENT edge kernel. Each block stages the 34 KB all-relation
// weight bank ONCE, then its warps grid-stride over edge pairs (e, e+half).
// Per iteration: 2 edges x 2 directions, 4 x-gathers issued before compute,
// weights via conflict-free LDS, outputs via red.global.add.v4.
__global__ void __launch_bounds__(256) edge_kernel(
    const float* __restrict__ x,
    const int* __restrict__ src,
    const int* __restrict__ tgt,
    const int* __restrict__ etype,
    const float* __restrict__ eweight,
    const float* __restrict__ blocks,
    float* __restrict__ out,
    int n_edges, int half)
{
    __shared__ float s_w[WBANK];   // s_w[r*512 + i*128 + b*4 + j]
    for (int idx = threadIdx.x; idx < WBANK; idx += 256) {
        int r = idx >> 9;
        int rem = idx & 511;
        int b = rem >> 4, i = (rem >> 2) & 3, j = rem & 3;
        s_w[r * BLK_STRIDE + i * 128 + b * 4 + j] = blocks[idx];
    }
    __syncthreads();

    int lane = threadIdx.x & 31;
    int warp0 = (blockIdx.x * 256 + threadIdx.x) >> 5;
    const int n_warps = (EDGE_BLOCKS * 256) >> 5;   // total warps in grid

    for (int e0 = warp0; e0 < half; e0 += n_warps) {
        int e1 = e0 + half;
        bool has1 = (e1 < n_edges);

        int s0 = src[e0], t0 = tgt[e0], r0 = etype[e0];
        float wgt0 = eweight[e0];
        int s1 = s0, t1 = t0, r1 = r0;
        float wgt1 = 0.f;
        if (has1) { s1 = src[e1]; t1 = tgt[e1]; r1 = etype[e1]; wgt1 = eweight[e1]; }

        // issue all 4 x-gathers up front (4 outstanding L2 loads)
        float4 xs0 = *reinterpret_cast<const float4*>(x + (size_t)s0 * DIM + lane * BS);
        float4 xt0 = *reinterpret_cast<const float4*>(x + (size_t)t0 * DIM + lane * BS);
        float4 xs1 = *reinterpret_cast<const float4*>(x + (size_t)s1 * DIM + lane * BS);
        float4 xt1 = *reinterpret_cast<const float4*>(x + (size_t)t1 * DIM + lane * BS);

        // ---- edge 0 ----
        {
            const float* wb = s_w + r0 * BLK_STRIDE + lane * 4;
            float4 w0 = *reinterpret_cast<const float4*>(wb);
            float4 w1 = *reinterpret_cast<const float4*>(wb + 128);
            float4 w2 = *reinterpret_cast<const float4*>(wb + 256);
            float4 w3 = *reinterpret_cast<const float4*>(wb + 384);

            float4 m1 = block_mm(xs0, w0, w1, w2, w3);
            m1.x *= wgt0; m1.y *= wgt0; m1.z *= wgt0; m1.w *= wgt0;
            float4 m2 = block_mm(xt0, w0, w1, w2, w3);
            m2.x *= wgt0; m2.y *= wgt0; m2.z *= wgt0; m2.w *= wgt0;

            red_add_v4(out + (size_t)t0 * DIM + lane * BS, m1);
            red_add_v4(out + (size_t)s0 * DIM + lane * BS, m2);
        }

        // ---- edge 1 ----
        if (has1) {
            const float* wb = s_w + r1 * BLK_STRIDE + lane * 4;
            float4 w0 = *reinterpret_cast<const float4*>(wb);
            float4 w1 = *reinterpret_cast<const float4*>(wb + 128);
            float4 w2 = *reinterpret_cast<const float4*>(wb + 256);
            float4 w3 = *reinterpret_cast<const float4*>(wb + 384);

            float4 m1 = block_mm(xs1, w0, w1, w2, w3);
            m1.x *= wgt1; m1.y *= wgt1; m1.z *= wgt1; m1.w *= wgt1;
            float4 m2 = block_mm(xt1, w0, w1, w2, w3);
            m2.x *= wgt1; m2.y *= wgt1; m2.z *= wgt1; m2.w *= wgt1;

            red_add_v4(out + (size_t)t1 * DIM + lane * BS, m1);
            red_add_v4(out + (size_t)s1 * DIM + lane * BS, m2);
        }
    }
}

extern "C" void kernel_launch(void* const* d_in, const int* in_sizes, int n_in,
                              void* d_out, int out_size)
{
    const float* x      = (const float*)d_in[0];
    const int*   mask   = (const int*)d_in[1];
    const int*   src    = (const int*)d_in[2];
    const int*   tgt    = (const int*)d_in[3];
    const int*   etype  = (const int*)d_in[4];
    const float* ew     = (const float*)d_in[5];
    const float* blocks = (const float*)d_in[6];
    float*       out    = (float*)d_out;

    int n_nodes = in_sizes[0] / DIM;
    int n_edges = in_sizes[2];
    int half = (n_edges + 1) / 2;

    // K1: out init (self-loop + mask)
    {
        int total_threads = n_nodes * 32;
        int grid = (total_threads + 255) / 256;
        self_loop_kernel<<<grid, 256>>>(x, mask, blocks, out, n_nodes);
    }
    // K2: persistent edge kernel (weight bank staged once per block)
    edge_kernel<<<EDGE_BLOCKS, 256>>>(x, src, tgt, etype, ew, blocks, out, n_edges, half);
}